// round 15
// baseline (speedup 1.0000x reference)
#include <cuda_runtime.h>
#include <cuda_bf16.h>
#include <cuda_fp16.h>
#include <cuda_fp8.h>
#include <cstdint>

// ---------------------------------------------------------------------------
// GAT layer with edge softmax — algebraically reduced, 3 kernels:
//
//   K1 uv_mma:    u = x@W_in[:64] -> fp8,  v = x@W_in[64:] + b_in -> fp8  (+zero S)
//   K2 edge:      S[t] += exp( leaky(u[src]+v[tgt]) . a_w + a_b )
//   K3 fin_gemm:  out = leaky( (S/(S+eps)) * (x@W_out + b_out) )
//                 p computed as fp16 x @ (fp16 W hi + lo): err ~2.8e-4 RMS,
//                 8 MMAs + 4 LDSM per m-tile, single staging tile, 4 CTAs/SM.
// ---------------------------------------------------------------------------

#define DI 64
#define NMAX 100000
#define SMS 148

__device__ unsigned char g_u[(size_t)NMAX * DI];   // fp8 e4m3
__device__ unsigned char g_v[(size_t)NMAX * DI];   // fp8 e4m3
__device__ float g_S[NMAX];

__device__ __forceinline__ float lrelu(float x) { return x >= 0.0f ? x : 0.01f * x; }

__device__ __forceinline__ uint32_t smem_u32(const void* p) {
    uint32_t a;
    asm("{ .reg .u64 t; cvta.to.shared.u64 t, %1; cvt.u32.u64 %0, t; }" : "=r"(a) : "l"(p));
    return a;
}

#define MMA_BF16(c, a, b) \
    asm volatile("mma.sync.aligned.m16n8k16.row.col.f32.bf16.bf16.f32 " \
        "{%0,%1,%2,%3}, {%4,%5,%6,%7}, {%8,%9}, {%0,%1,%2,%3};" \
        : "+f"((c)[0]), "+f"((c)[1]), "+f"((c)[2]), "+f"((c)[3]) \
        : "r"((a)[0]), "r"((a)[1]), "r"((a)[2]), "r"((a)[3]), \
          "r"((b)[0]), "r"((b)[1]))

#define MMA_F16(c, a, b) \
    asm volatile("mma.sync.aligned.m16n8k16.row.col.f32.f16.f16.f32 " \
        "{%0,%1,%2,%3}, {%4,%5,%6,%7}, {%8,%9}, {%0,%1,%2,%3};" \
        : "+f"((c)[0]), "+f"((c)[1]), "+f"((c)[2]), "+f"((c)[3]) \
        : "r"((a)[0]), "r"((a)[1]), "r"((a)[2]), "r"((a)[3]), \
          "r"((b)[0]), "r"((b)[1]))

#define LDSM4(r, addr) \
    asm volatile("ldmatrix.sync.aligned.m8n8.x4.shared.b16 {%0,%1,%2,%3}, [%4];" \
        : "=r"((r)[0]), "=r"((r)[1]), "=r"((r)[2]), "=r"((r)[3]) : "r"(addr))

#define A_STRIDE 144
#define A_BYTES  (128 * A_STRIDE)           // 18432

__device__ __forceinline__ uint32_t pack_bf16x2(float a, float b) {
    __nv_bfloat162 h = __floats2bfloat162_rn(a, b);
    return *(uint32_t*)&h;
}
__device__ __forceinline__ uint32_t pack_h2(float a, float b) {
    __half2 h = __floats2half2_rn(a, b);
    return *(uint32_t*)&h;
}
__device__ __forceinline__ uint16_t pack_fp8x2(float a, float b) {
    return (uint16_t)__nv_cvt_float2_to_fp8x2(make_float2(a, b), __NV_SATFINITE, __NV_E4M3);
}
__device__ __forceinline__ __half2 fp8pair_to_h2(uint32_t w, int hi) {
    __nv_fp8x2_storage_t s2 = (__nv_fp8x2_storage_t)(hi ? (w >> 16) : (w & 0xFFFFu));
    __half2_raw r = __nv_cvt_fp8x2_to_halfraw2(s2, __NV_E4M3);
    return *(__half2*)&r;
}

// swizzled staging address for (row, col-byte) in a [32 x 128B] tile
__device__ __forceinline__ uint32_t stg_sw(int row, int col) {
    return (uint32_t)(row * 128 + (col ^ ((row & 7) << 4)));
}

// ---------------------------------------------------------------------------
// Kernel 1 (persistent): uv = x @ W_in (+b_in on v half) -> fp8. Zeroes g_S.
// ---------------------------------------------------------------------------
#define UV_STAGE_OFF A_BYTES
#define UV_SMEM (A_BYTES + 2 * 4096)     // 26624

__global__ void __launch_bounds__(256, 4) uv_mma(
    const float* __restrict__ x, const float* __restrict__ W_in,
    const float* __restrict__ b_in, int n, int nTiles)
{
    __shared__ __align__(16) char smem[UV_SMEM];   // A_hi | stage x2 (4KB each)
    const uint32_t sb = smem_u32(smem);
    const int tid  = threadIdx.x;
    const int w    = tid >> 5;
    const int lane = tid & 31;
    const int g    = lane >> 2;
    const int t    = lane & 3;

    for (int zi = blockIdx.x * 256 + tid; zi < n; zi += gridDim.x * 256)
        g_S[zi] = 0.0f;

    uint32_t Buv[2][4][2];
#pragma unroll
    for (int tt = 0; tt < 2; tt++) {
        const int jc = 16 * w + 8 * tt + g;
        const int j  = (jc < 64) ? jc : (jc - 64);
        const int kb = (jc < 64) ? 0 : 64;
#pragma unroll
        for (int s = 0; s < 4; s++) {
            const int k0 = 16 * s + 2 * t;
            Buv[tt][s][0] = pack_bf16x2(__ldg(&W_in[(kb + k0) * 64 + j]),     __ldg(&W_in[(kb + k0 + 1) * 64 + j]));
            Buv[tt][s][1] = pack_bf16x2(__ldg(&W_in[(kb + k0 + 8) * 64 + j]), __ldg(&W_in[(kb + k0 + 9) * 64 + j]));
        }
    }
    float bv[2][2];
    if (w >= 4) {
#pragma unroll
        for (int tt = 0; tt < 2; tt++) {
            const int jv = 16 * w + 8 * tt + 2 * t - 64;
            bv[tt][0] = b_in[jv]; bv[tt][1] = b_in[jv + 1];
        }
    }

    const int lrow = lane & 15;
    const int lcol = (lane >> 4) * 16;

    for (int tile = blockIdx.x; tile < nTiles; tile += gridDim.x) {
        const int base = tile * 128;
        __syncthreads();   // prior tile's LDSM/stage reads done before overwrite

        for (int i = tid; i < 128 * 16; i += 256) {
            const int node = i >> 4, kc = i & 15;
            const int gn = base + node;
            float4 xv = make_float4(0.f, 0.f, 0.f, 0.f);
            if (gn < n) xv = *(const float4*)&x[(size_t)gn * 64 + 4 * kc];
            uint2 hi;
            hi.x = pack_bf16x2(xv.x, xv.y);
            hi.y = pack_bf16x2(xv.z, xv.w);
            *(uint2*)(smem + node * A_STRIDE + kc * 8) = hi;
        }
        __syncthreads();

#pragma unroll 1
        for (int mtg = 0; mtg < 4; mtg++) {
            char* stage = smem + UV_STAGE_OFF + (mtg & 1) * 4096;

#pragma unroll
            for (int mp = 0; mp < 2; mp++) {
                const int m0 = 32 * mtg + 16 * mp;

                uint32_t ah[4][4];
#pragma unroll
                for (int s = 0; s < 4; s++)
                    LDSM4(ah[s], sb + (uint32_t)((m0 + lrow) * A_STRIDE + 32 * s + lcol));

                float c0[4] = {0.f, 0.f, 0.f, 0.f};
                float c1[4] = {0.f, 0.f, 0.f, 0.f};
#pragma unroll
                for (int s = 0; s < 4; s++) {
                    MMA_BF16(c0, ah[s], Buv[0][s]);
                    MMA_BF16(c1, ah[s], Buv[1][s]);
                }

#pragma unroll
                for (int tt = 0; tt < 2; tt++) {
                    const float* c = tt ? c1 : c0;
                    const int col = 16 * w + 8 * tt + 2 * t;
                    float a0 = c[0], a1 = c[1], a2 = c[2], a3 = c[3];
                    if (w >= 4) { a0 += bv[tt][0]; a1 += bv[tt][1]; a2 += bv[tt][0]; a3 += bv[tt][1]; }
                    const int r0 = 16 * mp + g;
                    *(uint16_t*)(stage + stg_sw(r0,     col)) = pack_fp8x2(a0, a1);
                    *(uint16_t*)(stage + stg_sw(r0 + 8, col)) = pack_fp8x2(a2, a3);
                }
            }
            __syncthreads();

            {
                const int node_l = tid >> 3;
                const int cg = (tid & 7) * 16;
                const int node = base + 32 * mtg + node_l;
                if (node < n) {
                    const float4 val = *(const float4*)(stage + stg_sw(node_l, cg));
                    if (cg < 64) *(float4*)&g_u[(size_t)node * 64 + cg]        = val;
                    else         *(float4*)&g_v[(size_t)node * 64 + (cg - 64)] = val;
                }
            }
        }
    }
}

// ---------------------------------------------------------------------------
// Kernel 2: 8-lanes-per-edge fp8 logit + exp + atomic segment sum (R12 form)
// ---------------------------------------------------------------------------
#define EDGES_PER_WARP 16

__global__ void __launch_bounds__(256) edge_kernel(
    const int* __restrict__ src, const int* __restrict__ tgt,
    const float* __restrict__ a_w, const float* __restrict__ a_b, int E)
{
    const int lane = threadIdx.x & 31;
    const int q  = lane >> 3;
    const int sl = lane & 7;
    const int warp = (blockIdx.x * 256 + threadIdx.x) >> 5;

    __half2 aw[4];
#pragma unroll
    for (int pc = 0; pc < 4; pc++)
        aw[pc] = __floats2half2_rn(__ldg(&a_w[8 * sl + 2 * pc]), __ldg(&a_w[8 * sl + 2 * pc + 1]));
    const float ab = a_b[0];
    const __half2 slope = __floats2half2_rn(0.01f, 0.01f);

    const int e0 = warp * EDGES_PER_WARP + q;

    int ee[4]; bool val[4];
#pragma unroll
    for (int i = 0; i < 4; i++) {
        const int e = e0 + 4 * i;
        val[i] = (e < E);
        ee[i] = val[i] ? e : (E - 1);
    }

    int tcur = __ldg(&tgt[ee[0]]);
    uint2 urb = *(const uint2*)&g_u[(size_t)__ldg(&src[ee[0]]) * 64 + 8 * sl];
    uint2 vrb = *(const uint2*)&g_v[(size_t)tcur * 64 + 8 * sl];

#pragma unroll
    for (int i = 0; i < 4; i++) {
        const uint2 ur = urb;
        const uint2 vr = vrb;
        const int tthis = tcur;

        if (i < 3) {
            const int s1 = __ldg(&src[ee[i + 1]]);
            tcur = __ldg(&tgt[ee[i + 1]]);
            urb = *(const uint2*)&g_u[(size_t)s1 * 64 + 8 * sl];
            vrb = *(const uint2*)&g_v[(size_t)tcur * 64 + 8 * sl];
        }

        __half2 acc = __floats2half2_rn(0.f, 0.f);
#pragma unroll
        for (int pc = 0; pc < 4; pc++) {
            const uint32_t uw = (pc < 2) ? ur.x : ur.y;
            const uint32_t vw = (pc < 2) ? vr.x : vr.y;
            const int h = pc & 1;
            const __half2 sum = __hadd2(fp8pair_to_h2(uw, h), fp8pair_to_h2(vw, h));
            const __half2 lr  = __hmax2(sum, __hmul2(sum, slope));
            acc = __hfma2(lr, aw[pc], acc);
        }
        float part = __half2float(__low2half(acc)) + __half2float(__high2half(acc));

        part += __shfl_xor_sync(0xffffffffu, part, 4);
        part += __shfl_xor_sync(0xffffffffu, part, 2);
        part += __shfl_xor_sync(0xffffffffu, part, 1);

        if (sl == 0 && val[i]) atomicAdd(&g_S[tthis], __expf(part + ab));
    }
}

// ---------------------------------------------------------------------------
// Kernel 3 (persistent): out = leaky( (S/(S+eps)) * (x @ W_out + b_out) )
// fp16 x @ 2-term fp16 W split: 8 MMAs + 4 LDSM per m-tile, single A tile.
// ---------------------------------------------------------------------------
#define FIN_SMEM A_BYTES   // 18432: A_h (fp16) only

__global__ void __launch_bounds__(256, 4) finalize_gemm(
    const float* __restrict__ x, const float* __restrict__ W_out,
    const float* __restrict__ b_out, float* __restrict__ out, int n, int nTiles)
{
    __shared__ __align__(16) char smem[FIN_SMEM];
    const uint32_t sb = smem_u32(smem);
    const int tid  = threadIdx.x;
    const int w    = tid >> 5;
    const int lane = tid & 31;
    const int g    = lane >> 2;
    const int t    = lane & 3;

    // B fragments: wh = fp16(W), wl = fp16(W - wh)  (W error ~2^-22)
    uint32_t BpH[4][2], BpL[4][2];
    {
        const int j = 8 * w + g;
#pragma unroll
        for (int s = 0; s < 4; s++) {
            const int k0 = 16 * s + 2 * t;
            float f00 = __ldg(&W_out[k0 * 64 + j]),       f01 = __ldg(&W_out[(k0 + 1) * 64 + j]);
            float f10 = __ldg(&W_out[(k0 + 8) * 64 + j]), f11 = __ldg(&W_out[(k0 + 9) * 64 + j]);
            __half h00 = __float2half_rn(f00), h01 = __float2half_rn(f01);
            __half h10 = __float2half_rn(f10), h11 = __float2half_rn(f11);
            BpH[s][0] = pack_h2(f00, f01);
            BpH[s][1] = pack_h2(f10, f11);
            BpL[s][0] = pack_h2(f00 - __half2float(h00), f01 - __half2float(h01));
            BpL[s][1] = pack_h2(f10 - __half2float(h10), f11 - __half2float(h11));
        }
    }
    const float bo0 = b_out[8 * w + 2 * t];
    const float bo1 = b_out[8 * w + 2 * t + 1];

    const int lrow = lane & 15;
    const int lcol = (lane >> 4) * 16;

    for (int tile = blockIdx.x; tile < nTiles; tile += gridDim.x) {
        const int base = tile * 128;
        __syncthreads();

        // stage x as fp16
        for (int i = tid; i < 128 * 16; i += 256) {
            const int node = i >> 4, kc = i & 15;
            const int gn = base + node;
            float4 xv = make_float4(0.f, 0.f, 0.f, 0.f);
            if (gn < n) xv = *(const float4*)&x[(size_t)gn * 64 + 4 * kc];
            uint2 hi;
            hi.x = pack_h2(xv.x, xv.y);
            hi.y = pack_h2(xv.z, xv.w);
            *(uint2*)(smem + node * A_STRIDE + kc * 8) = hi;
        }
        __syncthreads();

#pragma unroll 1
        for (int mt = 0; mt < 8; mt++) {
            const int m0 = 16 * mt;
            uint32_t ah[4][4];
#pragma unroll
            for (int s = 0; s < 4; s++)
                LDSM4(ah[s], sb + (uint32_t)((m0 + lrow) * A_STRIDE + 32 * s + lcol));

            float cH[4] = {0.f, 0.f, 0.f, 0.f};
            float cL[4] = {0.f, 0.f, 0.f, 0.f};
#pragma unroll
            for (int s = 0; s < 4; s++) {
                MMA_F16(cH, ah[s], BpH[s]);
                MMA_F16(cL, ah[s], BpL[s]);
            }

            const int node_lo = base + m0 + g;
            const int node_hi = node_lo + 8;
            const int cp = 8 * w + 2 * t;
            if (node_lo < n) {
                const float S = g_S[node_lo];
                const float f = S / (S + 1e-6f);
                *(float2*)&out[(size_t)node_lo * 64 + cp] = make_float2(
                    lrelu(f * (cH[0] + cL[0] + bo0)),
                    lrelu(f * (cH[1] + cL[1] + bo1)));
            }
            if (node_hi < n) {
                const float S = g_S[node_hi];
                const float f = S / (S + 1e-6f);
                *(float2*)&out[(size_t)node_hi * 64 + cp] = make_float2(
                    lrelu(f * (cH[2] + cL[2] + bo0)),
                    lrelu(f * (cH[3] + cL[3] + bo1)));
            }
        }
    }
}

// ---------------------------------------------------------------------------
extern "C" void kernel_launch(void* const* d_in, const int* in_sizes, int n_in,
                              void* d_out, int out_size)
{
    const float* x     = (const float*)d_in[0];
    const int*   src   = (const int*)  d_in[1];
    const int*   tgt   = (const int*)  d_in[2];
    const float* W_in  = (const float*)d_in[3];
    const float* b_in  = (const float*)d_in[4];
    const float* a_w   = (const float*)d_in[5];
    const float* a_b   = (const float*)d_in[6];
    const float* W_out = (const float*)d_in[7];
    const float* b_out = (const float*)d_in[8];
    float* out = (float*)d_out;

    const int N = in_sizes[0] / DI;
    const int E = in_sizes[1];
    const int nTiles = (N + 127) / 128;

    int uv_grid = 4 * SMS;  if (uv_grid > nTiles) uv_grid = nTiles;
    uv_mma<<<uv_grid, 256>>>(x, W_in, b_in, N, nTiles);

    const int warps = (E + EDGES_PER_WARP - 1) / EDGES_PER_WARP;
    const int edge_blocks = (warps + 7) / 8;
    edge_kernel<<<edge_blocks, 256>>>(src, tgt, a_w, a_b, E);

    int fin_grid = 4 * SMS;  if (fin_grid > nTiles) fin_grid = nTiles;
    finalize_gemm<<<fin_grid, 256>>>(x, W_out, b_out, out, N, nTiles);
}

// round 16
// speedup vs baseline: 1.1036x; 1.1036x over previous
#include <cuda_runtime.h>
#include <cuda_bf16.h>
#include <cuda_fp16.h>
#include <cuda_fp8.h>
#include <cstdint>

// ---------------------------------------------------------------------------
// GAT layer with edge softmax — algebraically reduced, 3 kernels:
//
//   K1 uv_mma:    u = x@W_in[:64] -> fp8,  v = x@W_in[64:] + b_in -> fp8  (+zero S)
//   K2 edge:      S[t] += exp( leaky(u[src]+v[tgt]) . a_w + a_b )
//   K3 fin_gemm:  out = leaky( (S/(S+eps)) * (x@W_out + b_out) )
//                 fp16 2-term split; p staged in smem -> 128B coalesced stores,
//                 S applied once per node at flush.
// ---------------------------------------------------------------------------

#define DI 64
#define NMAX 100000
#define SMS 148

__device__ unsigned char g_u[(size_t)NMAX * DI];   // fp8 e4m3
__device__ unsigned char g_v[(size_t)NMAX * DI];   // fp8 e4m3
__device__ float g_S[NMAX];

__device__ __forceinline__ float lrelu(float x) { return x >= 0.0f ? x : 0.01f * x; }

__device__ __forceinline__ uint32_t smem_u32(const void* p) {
    uint32_t a;
    asm("{ .reg .u64 t; cvta.to.shared.u64 t, %1; cvt.u32.u64 %0, t; }" : "=r"(a) : "l"(p));
    return a;
}

#define MMA_BF16(c, a, b) \
    asm volatile("mma.sync.aligned.m16n8k16.row.col.f32.bf16.bf16.f32 " \
        "{%0,%1,%2,%3}, {%4,%5,%6,%7}, {%8,%9}, {%0,%1,%2,%3};" \
        : "+f"((c)[0]), "+f"((c)[1]), "+f"((c)[2]), "+f"((c)[3]) \
        : "r"((a)[0]), "r"((a)[1]), "r"((a)[2]), "r"((a)[3]), \
          "r"((b)[0]), "r"((b)[1]))

#define MMA_F16(c, a, b) \
    asm volatile("mma.sync.aligned.m16n8k16.row.col.f32.f16.f16.f32 " \
        "{%0,%1,%2,%3}, {%4,%5,%6,%7}, {%8,%9}, {%0,%1,%2,%3};" \
        : "+f"((c)[0]), "+f"((c)[1]), "+f"((c)[2]), "+f"((c)[3]) \
        : "r"((a)[0]), "r"((a)[1]), "r"((a)[2]), "r"((a)[3]), \
          "r"((b)[0]), "r"((b)[1]))

#define LDSM4(r, addr) \
    asm volatile("ldmatrix.sync.aligned.m8n8.x4.shared.b16 {%0,%1,%2,%3}, [%4];" \
        : "=r"((r)[0]), "=r"((r)[1]), "=r"((r)[2]), "=r"((r)[3]) : "r"(addr))

#define A_STRIDE 144
#define A_BYTES  (128 * A_STRIDE)           // 18432

__device__ __forceinline__ uint32_t pack_bf16x2(float a, float b) {
    __nv_bfloat162 h = __floats2bfloat162_rn(a, b);
    return *(uint32_t*)&h;
}
__device__ __forceinline__ uint32_t pack_h2(float a, float b) {
    __half2 h = __floats2half2_rn(a, b);
    return *(uint32_t*)&h;
}
__device__ __forceinline__ uint16_t pack_fp8x2(float a, float b) {
    return (uint16_t)__nv_cvt_float2_to_fp8x2(make_float2(a, b), __NV_SATFINITE, __NV_E4M3);
}
__device__ __forceinline__ __half2 fp8pair_to_h2(uint32_t w, int hi) {
    __nv_fp8x2_storage_t s2 = (__nv_fp8x2_storage_t)(hi ? (w >> 16) : (w & 0xFFFFu));
    __half2_raw r = __nv_cvt_fp8x2_to_halfraw2(s2, __NV_E4M3);
    return *(__half2*)&r;
}

// swizzled staging address for (row, col-byte) in a [32 x 128B] tile (fp8 uv)
__device__ __forceinline__ uint32_t stg_sw(int row, int col) {
    return (uint32_t)(row * 128 + (col ^ (((row) & 7) << 4)));
}
// swizzled staging address for (row, col-byte) in a [32 x 256B] tile (fp32 p)
__device__ __forceinline__ uint32_t stg256(int row, int col) {
    return (uint32_t)(row * 256 + (col ^ (((row) & 7) << 5)));
}

// ---------------------------------------------------------------------------
// Kernel 1 (persistent): uv = x @ W_in (+b_in on v half) -> fp8. Zeroes g_S.
// ---------------------------------------------------------------------------
#define UV_STAGE_OFF A_BYTES
#define UV_SMEM (A_BYTES + 2 * 4096)     // 26624

__global__ void __launch_bounds__(256, 4) uv_mma(
    const float* __restrict__ x, const float* __restrict__ W_in,
    const float* __restrict__ b_in, int n, int nTiles)
{
    __shared__ __align__(16) char smem[UV_SMEM];   // A_hi | stage x2 (4KB each)
    const uint32_t sb = smem_u32(smem);
    const int tid  = threadIdx.x;
    const int w    = tid >> 5;
    const int lane = tid & 31;
    const int g    = lane >> 2;
    const int t    = lane & 3;

    for (int zi = blockIdx.x * 256 + tid; zi < n; zi += gridDim.x * 256)
        g_S[zi] = 0.0f;

    uint32_t Buv[2][4][2];
#pragma unroll
    for (int tt = 0; tt < 2; tt++) {
        const int jc = 16 * w + 8 * tt + g;
        const int j  = (jc < 64) ? jc : (jc - 64);
        const int kb = (jc < 64) ? 0 : 64;
#pragma unroll
        for (int s = 0; s < 4; s++) {
            const int k0 = 16 * s + 2 * t;
            Buv[tt][s][0] = pack_bf16x2(__ldg(&W_in[(kb + k0) * 64 + j]),     __ldg(&W_in[(kb + k0 + 1) * 64 + j]));
            Buv[tt][s][1] = pack_bf16x2(__ldg(&W_in[(kb + k0 + 8) * 64 + j]), __ldg(&W_in[(kb + k0 + 9) * 64 + j]));
        }
    }
    float bv[2][2];
    if (w >= 4) {
#pragma unroll
        for (int tt = 0; tt < 2; tt++) {
            const int jv = 16 * w + 8 * tt + 2 * t - 64;
            bv[tt][0] = b_in[jv]; bv[tt][1] = b_in[jv + 1];
        }
    }

    const int lrow = lane & 15;
    const int lcol = (lane >> 4) * 16;

    for (int tile = blockIdx.x; tile < nTiles; tile += gridDim.x) {
        const int base = tile * 128;
        __syncthreads();   // prior tile's LDSM/stage reads done before overwrite

        for (int i = tid; i < 128 * 16; i += 256) {
            const int node = i >> 4, kc = i & 15;
            const int gn = base + node;
            float4 xv = make_float4(0.f, 0.f, 0.f, 0.f);
            if (gn < n) xv = *(const float4*)&x[(size_t)gn * 64 + 4 * kc];
            uint2 hi;
            hi.x = pack_bf16x2(xv.x, xv.y);
            hi.y = pack_bf16x2(xv.z, xv.w);
            *(uint2*)(smem + node * A_STRIDE + kc * 8) = hi;
        }
        __syncthreads();

#pragma unroll 1
        for (int mtg = 0; mtg < 4; mtg++) {
            char* stage = smem + UV_STAGE_OFF + (mtg & 1) * 4096;

#pragma unroll
            for (int mp = 0; mp < 2; mp++) {
                const int m0 = 32 * mtg + 16 * mp;

                uint32_t ah[4][4];
#pragma unroll
                for (int s = 0; s < 4; s++)
                    LDSM4(ah[s], sb + (uint32_t)((m0 + lrow) * A_STRIDE + 32 * s + lcol));

                float c0[4] = {0.f, 0.f, 0.f, 0.f};
                float c1[4] = {0.f, 0.f, 0.f, 0.f};
#pragma unroll
                for (int s = 0; s < 4; s++) {
                    MMA_BF16(c0, ah[s], Buv[0][s]);
                    MMA_BF16(c1, ah[s], Buv[1][s]);
                }

#pragma unroll
                for (int tt = 0; tt < 2; tt++) {
                    const float* c = tt ? c1 : c0;
                    const int col = 16 * w + 8 * tt + 2 * t;
                    float a0 = c[0], a1 = c[1], a2 = c[2], a3 = c[3];
                    if (w >= 4) { a0 += bv[tt][0]; a1 += bv[tt][1]; a2 += bv[tt][0]; a3 += bv[tt][1]; }
                    const int r0 = 16 * mp + g;
                    *(uint16_t*)(stage + stg_sw(r0,     col)) = pack_fp8x2(a0, a1);
                    *(uint16_t*)(stage + stg_sw(r0 + 8, col)) = pack_fp8x2(a2, a3);
                }
            }
            __syncthreads();

            {
                const int node_l = tid >> 3;
                const int cg = (tid & 7) * 16;
                const int node = base + 32 * mtg + node_l;
                if (node < n) {
                    const float4 val = *(const float4*)(stage + stg_sw(node_l, cg));
                    if (cg < 64) *(float4*)&g_u[(size_t)node * 64 + cg]        = val;
                    else         *(float4*)&g_v[(size_t)node * 64 + (cg - 64)] = val;
                }
            }
        }
    }
}

// ---------------------------------------------------------------------------
// Kernel 2: 8-lanes-per-edge fp8 logit + exp + atomic segment sum
// ---------------------------------------------------------------------------
#define EDGES_PER_WARP 16

__global__ void __launch_bounds__(256) edge_kernel(
    const int* __restrict__ src, const int* __restrict__ tgt,
    const float* __restrict__ a_w, const float* __restrict__ a_b, int E)
{
    const int lane = threadIdx.x & 31;
    const int q  = lane >> 3;
    const int sl = lane & 7;
    const int warp = (blockIdx.x * 256 + threadIdx.x) >> 5;

    __half2 aw[4];
#pragma unroll
    for (int pc = 0; pc < 4; pc++)
        aw[pc] = __floats2half2_rn(__ldg(&a_w[8 * sl + 2 * pc]), __ldg(&a_w[8 * sl + 2 * pc + 1]));
    const float ab = a_b[0];
    const __half2 slope = __floats2half2_rn(0.01f, 0.01f);

    const int e0 = warp * EDGES_PER_WARP + q;

    int ee[4]; bool val[4];
#pragma unroll
    for (int i = 0; i < 4; i++) {
        const int e = e0 + 4 * i;
        val[i] = (e < E);
        ee[i] = val[i] ? e : (E - 1);
    }

    int tcur = __ldg(&tgt[ee[0]]);
    uint2 urb = *(const uint2*)&g_u[(size_t)__ldg(&src[ee[0]]) * 64 + 8 * sl];
    uint2 vrb = *(const uint2*)&g_v[(size_t)tcur * 64 + 8 * sl];

#pragma unroll
    for (int i = 0; i < 4; i++) {
        const uint2 ur = urb;
        const uint2 vr = vrb;
        const int tthis = tcur;

        if (i < 3) {
            const int s1 = __ldg(&src[ee[i + 1]]);
            tcur = __ldg(&tgt[ee[i + 1]]);
            urb = *(const uint2*)&g_u[(size_t)s1 * 64 + 8 * sl];
            vrb = *(const uint2*)&g_v[(size_t)tcur * 64 + 8 * sl];
        }

        __half2 acc = __floats2half2_rn(0.f, 0.f);
#pragma unroll
        for (int pc = 0; pc < 4; pc++) {
            const uint32_t uw = (pc < 2) ? ur.x : ur.y;
            const uint32_t vw = (pc < 2) ? vr.x : vr.y;
            const int h = pc & 1;
            const __half2 sum = __hadd2(fp8pair_to_h2(uw, h), fp8pair_to_h2(vw, h));
            const __half2 lr  = __hmax2(sum, __hmul2(sum, slope));
            acc = __hfma2(lr, aw[pc], acc);
        }
        float part = __half2float(__low2half(acc)) + __half2float(__high2half(acc));

        part += __shfl_xor_sync(0xffffffffu, part, 4);
        part += __shfl_xor_sync(0xffffffffu, part, 2);
        part += __shfl_xor_sync(0xffffffffu, part, 1);

        if (sl == 0 && val[i]) atomicAdd(&g_S[tthis], __expf(part + ab));
    }
}

// ---------------------------------------------------------------------------
// Kernel 3 (persistent): out = leaky( (S/(S+eps)) * (x @ W_out + b_out) )
// fp16 x @ 2-term fp16 W split. p staged in swizzled smem [32x256B] x2,
// flushed as 128B-coalesced stores with S applied once per node.
// ---------------------------------------------------------------------------
#define FIN_STAGE_OFF A_BYTES
#define FIN_SMEM (A_BYTES + 2 * 8192)   // 18432 + 16384 = 34816

__global__ void __launch_bounds__(256, 4) finalize_gemm(
    const float* __restrict__ x, const float* __restrict__ W_out,
    const float* __restrict__ b_out, float* __restrict__ out, int n, int nTiles)
{
    __shared__ __align__(16) char smem[FIN_SMEM];
    const uint32_t sb = smem_u32(smem);
    const int tid  = threadIdx.x;
    const int w    = tid >> 5;
    const int lane = tid & 31;
    const int g    = lane >> 2;
    const int t    = lane & 3;

    // B fragments: wh = fp16(W), wl = fp16(W - wh)
    uint32_t BpH[4][2], BpL[4][2];
    {
        const int j = 8 * w + g;
#pragma unroll
        for (int s = 0; s < 4; s++) {
            const int k0 = 16 * s + 2 * t;
            float f00 = __ldg(&W_out[k0 * 64 + j]),       f01 = __ldg(&W_out[(k0 + 1) * 64 + j]);
            float f10 = __ldg(&W_out[(k0 + 8) * 64 + j]), f11 = __ldg(&W_out[(k0 + 9) * 64 + j]);
            __half h00 = __float2half_rn(f00), h01 = __float2half_rn(f01);
            __half h10 = __float2half_rn(f10), h11 = __float2half_rn(f11);
            BpH[s][0] = pack_h2(f00, f01);
            BpH[s][1] = pack_h2(f10, f11);
            BpL[s][0] = pack_h2(f00 - __half2float(h00), f01 - __half2float(h01));
            BpL[s][1] = pack_h2(f10 - __half2float(h10), f11 - __half2float(h11));
        }
    }
    const float bo0 = b_out[8 * w + 2 * t];
    const float bo1 = b_out[8 * w + 2 * t + 1];

    const int lrow = lane & 15;
    const int lcol = (lane >> 4) * 16;

    for (int tile = blockIdx.x; tile < nTiles; tile += gridDim.x) {
        const int base = tile * 128;
        __syncthreads();

        // stage x as fp16
        for (int i = tid; i < 128 * 16; i += 256) {
            const int node = i >> 4, kc = i & 15;
            const int gn = base + node;
            float4 xv = make_float4(0.f, 0.f, 0.f, 0.f);
            if (gn < n) xv = *(const float4*)&x[(size_t)gn * 64 + 4 * kc];
            uint2 hi;
            hi.x = pack_h2(xv.x, xv.y);
            hi.y = pack_h2(xv.z, xv.w);
            *(uint2*)(smem + node * A_STRIDE + kc * 8) = hi;
        }
        __syncthreads();

#pragma unroll 1
        for (int mtg = 0; mtg < 4; mtg++) {          // 4 groups of 2 m-tiles
            char* stage = smem + FIN_STAGE_OFF + (mtg & 1) * 8192;  // [32 x 256B]

#pragma unroll
            for (int mp = 0; mp < 2; mp++) {
                const int m0 = 32 * mtg + 16 * mp;
                uint32_t ah[4][4];
#pragma unroll
                for (int s = 0; s < 4; s++)
                    LDSM4(ah[s], sb + (uint32_t)((m0 + lrow) * A_STRIDE + 32 * s + lcol));

                float cH[4] = {0.f, 0.f, 0.f, 0.f};
                float cL[4] = {0.f, 0.f, 0.f, 0.f};
#pragma unroll
                for (int s = 0; s < 4; s++) {
                    MMA_F16(cH, ah[s], BpH[s]);
                    MMA_F16(cL, ah[s], BpL[s]);
                }

                // raw p (+bias) into swizzled stage
                const int col = (8 * w + 2 * t) * 4;   // byte col in 256B row
                const int r0 = 16 * mp + g;
                *(float2*)(stage + stg256(r0,     col)) = make_float2(cH[0] + cL[0] + bo0, cH[1] + cL[1] + bo1);
                *(float2*)(stage + stg256(r0 + 8, col)) = make_float2(cH[2] + cL[2] + bo0, cH[3] + cL[3] + bo1);
            }
            __syncthreads();

            // flush: 2 passes x (16 nodes x 16 chunks of 16B) -> 128B stores
#pragma unroll
            for (int pass = 0; pass < 2; pass++) {
                const int node_l = (tid >> 4) + 16 * pass;      // 0..31
                const int cg = (tid & 15) * 16;                 // byte col
                const int node = base + 32 * mtg + node_l;
                if (node < n) {
                    float4 pv = *(const float4*)(stage + stg256(node_l, cg));
                    const float S = g_S[node];
                    const float f = S / (S + 1e-6f);
                    float4 o;
                    o.x = lrelu(f * pv.x);
                    o.y = lrelu(f * pv.y);
                    o.z = lrelu(f * pv.z);
                    o.w = lrelu(f * pv.w);
                    *(float4*)&out[(size_t)node * 64 + (cg >> 2)] = o;
                }
            }
            // double buffer: group mtg+2 reuses this buffer; the sync inside
            // group mtg+1 orders this read before that overwrite.
        }
    }
}

// ---------------------------------------------------------------------------
extern "C" void kernel_launch(void* const* d_in, const int* in_sizes, int n_in,
                              void* d_out, int out_size)
{
    const float* x     = (const float*)d_in[0];
    const int*   src   = (const int*)  d_in[1];
    const int*   tgt   = (const int*)  d_in[2];
    const float* W_in  = (const float*)d_in[3];
    const float* b_in  = (const float*)d_in[4];
    const float* a_w   = (const float*)d_in[5];
    const float* a_b   = (const float*)d_in[6];
    const float* W_out = (const float*)d_in[7];
    const float* b_out = (const float*)d_in[8];
    float* out = (float*)d_out;

    const int N = in_sizes[0] / DI;
    const int E = in_sizes[1];
    const int nTiles = (N + 127) / 128;

    int uv_grid = 4 * SMS;  if (uv_grid > nTiles) uv_grid = nTiles;
    uv_mma<<<uv_grid, 256>>>(x, W_in, b_in, N, nTiles);

    const int warps = (E + EDGES_PER_WARP - 1) / EDGES_PER_WARP;
    const int edge_blocks = (warps + 7) / 8;
    edge_kernel<<<edge_blocks, 256>>>(src, tgt, a_w, a_b, E);

    int fin_grid = 4 * SMS;  if (fin_grid > nTiles) fin_grid = nTiles;
    finalize_gemm<<<fin_grid, 256>>>(x, W_out, b_out, out, N, nTiles);
}